// round 15
// baseline (speedup 1.0000x reference)
#include <cuda_runtime.h>
#include <cuda_fp16.h>
#include <cstdint>
#include <cmath>

#define NTOK 8192       // B*S
#define DDIM 1024
#define FDIM 4096
#define NEXP 4
#define SEG  8192       // fixed rows per expert segment
#define RTOT (NEXP * SEG)   // 32768 packed rows

// ---------------- device scratch (module-load; no runtime alloc) ------------
__device__ int g_count[NEXP];
__device__ int g_list[NEXP][NTOK];
__device__ int g_rowslot[RTOT];
__device__ __half g_a[(size_t)RTOT * DDIM];           // packed x as fp16
__device__ __half g_h[(size_t)RTOT * FDIM];           // h as fp16
__device__ __half g_w1[(size_t)NEXP * DDIM * FDIM];   // [E][D][F] fp16(W1)
__device__ __half g_w2[(size_t)NEXP * FDIM * DDIM];   // [E][F][D] fp16(W2)

// ---------------- helpers ----------------------------------------------------
__device__ __forceinline__ uint32_t smem_u32(const void* p) {
    uint32_t a;
    asm("{ .reg .u64 t; cvta.to.shared.u64 t, %1; cvt.u32.u64 %0, t; }" : "=r"(a) : "l"(p));
    return a;
}
#define CP_ASYNC16(dst, src) \
    asm volatile("cp.async.cg.shared.global [%0], [%1], 16;" :: "r"(dst), "l"(src))
#define CP_COMMIT() asm volatile("cp.async.commit_group;" ::: "memory")
#define CP_WAIT1()  asm volatile("cp.async.wait_group 1;" ::: "memory")
#define CP_WAIT0()  asm volatile("cp.async.wait_group 0;" ::: "memory")

__device__ __forceinline__ void ldm_x4(uint32_t* r, uint32_t addr) {
    asm volatile("ldmatrix.sync.aligned.m8n8.x4.shared.b16 {%0,%1,%2,%3}, [%4];"
                 : "=r"(r[0]), "=r"(r[1]), "=r"(r[2]), "=r"(r[3]) : "r"(addr));
}
__device__ __forceinline__ void ldm_x4_t(uint32_t* r, uint32_t addr) {
    asm volatile("ldmatrix.sync.aligned.m8n8.x4.trans.shared.b16 {%0,%1,%2,%3}, [%4];"
                 : "=r"(r[0]), "=r"(r[1]), "=r"(r[2]), "=r"(r[3]) : "r"(addr));
}
__device__ __forceinline__ void mma16816(float* c, const uint32_t* a, uint32_t b0, uint32_t b1) {
    asm("mma.sync.aligned.m16n8k16.row.col.f32.f16.f16.f32 "
        "{%0,%1,%2,%3}, {%4,%5,%6,%7}, {%8,%9}, {%0,%1,%2,%3};"
        : "+f"(c[0]), "+f"(c[1]), "+f"(c[2]), "+f"(c[3])
        : "r"(a[0]), "r"(a[1]), "r"(a[2]), "r"(a[3]), "r"(b0), "r"(b1));
}
__device__ __forceinline__ uint32_t pack2h(__half a, __half b) {
    return (uint32_t)__half_as_ushort(a) | ((uint32_t)__half_as_ushort(b) << 16);
}

// ---------------- prep: reset counters + zero out + cvt W1,W2 (one launch) ---
static constexpr int NW4   = NEXP * DDIM * FDIM / 4;
static constexpr int NOUT4 = NTOK * DDIM / 4;
static constexpr int NPREP = 2 * NW4 + NOUT4;

__global__ void k_prep(const float* __restrict__ W1, const float* __restrict__ W2,
                       float* __restrict__ out) {
    int i = blockIdx.x * blockDim.x + threadIdx.x;
    if (i < 4) g_count[i] = 0;
    if (i >= NPREP) return;
    if (i < NW4) {
        float4 v = reinterpret_cast<const float4*>(W1)[i];
        reinterpret_cast<uint2*>(g_w1)[i] =
            make_uint2(pack2h(__float2half(v.x), __float2half(v.y)),
                       pack2h(__float2half(v.z), __float2half(v.w)));
    } else if (i < 2 * NW4) {
        int j = i - NW4;
        float4 v = reinterpret_cast<const float4*>(W2)[j];
        reinterpret_cast<uint2*>(g_w2)[j] =
            make_uint2(pack2h(__float2half(v.x), __float2half(v.y)),
                       pack2h(__float2half(v.z), __float2half(v.w)));
    } else {
        reinterpret_cast<float4*>(out)[i - 2 * NW4] = make_float4(0.f, 0.f, 0.f, 0.f);
    }
}

// ---------------- gate --------------------------------------------------------
__global__ void k_gate(const float* __restrict__ x, const float* __restrict__ Wg,
                       const float* __restrict__ bg) {
    int t = blockIdx.x, tid = threadIdx.x;
    const float* xr = x + (size_t)t * DDIM;
    float s0 = 0.f, s1 = 0.f, s2 = 0.f, s3 = 0.f;
    for (int i = tid; i < DDIM; i += 128) {
        float xv = xr[i];
        float4 w = *reinterpret_cast<const float4*>(Wg + (size_t)i * 4);
        s0 += xv * w.x; s1 += xv * w.y; s2 += xv * w.z; s3 += xv * w.w;
    }
    #pragma unroll
    for (int o = 16; o; o >>= 1) {
        s0 += __shfl_down_sync(~0u, s0, o); s1 += __shfl_down_sync(~0u, s1, o);
        s2 += __shfl_down_sync(~0u, s2, o); s3 += __shfl_down_sync(~0u, s3, o);
    }
    __shared__ float red[4][4];
    if ((tid & 31) == 0) { int w = tid >> 5; red[w][0]=s0; red[w][1]=s1; red[w][2]=s2; red[w][3]=s3; }
    __syncthreads();
    if (tid == 0) {
        float l[4];
        #pragma unroll
        for (int e = 0; e < 4; e++) l[e] = red[0][e]+red[1][e]+red[2][e]+red[3][e]+bg[e];
        int e0 = 0;
        #pragma unroll
        for (int e = 1; e < 4; e++) if (l[e] > l[e0]) e0 = e;
        int e1 = -1;
        #pragma unroll
        for (int e = 0; e < 4; e++) { if (e == e0) continue; if (e1 < 0 || l[e] > l[e1]) e1 = e; }
        int p0 = atomicAdd(&g_count[e0], 1); g_list[e0][p0] = t * 2;
        int p1 = atomicAdd(&g_count[e1], 1); g_list[e1][p1] = t * 2 + 1;
    }
}

// ---------------- pack: gather + fp16 convert into fixed segments ------------
__global__ void k_pack(const float* __restrict__ x) {
    int b = blockIdx.x;
    int e = b >> 13;                    // SEG = 8192
    int j = b & (SEG - 1);
    int cnt = g_count[e];
    int tid = threadIdx.x;
    __half* dh = g_a + (size_t)b * DDIM;
    if (j < cnt) {
        int slot = g_list[e][j];
        if (tid == 0) g_rowslot[b] = slot;
        const float4* src = reinterpret_cast<const float4*>(x + (size_t)(slot >> 1) * DDIM);
        float4 v0 = src[tid * 2], v1 = src[tid * 2 + 1];
        uint4 uh = make_uint4(
            pack2h(__float2half(v0.x), __float2half(v0.y)),
            pack2h(__float2half(v0.z), __float2half(v0.w)),
            pack2h(__float2half(v1.x), __float2half(v1.y)),
            pack2h(__float2half(v1.z), __float2half(v1.w)));
        *reinterpret_cast<uint4*>(dh + tid * 8) = uh;
    } else if (j < ((cnt + 127) & ~127)) {
        if (tid == 0) g_rowslot[b] = -1;
        *reinterpret_cast<uint4*>(dh + tid * 8) = make_uint4(0, 0, 0, 0);
    }
}

// ---------------- HMMA grouped GEMM -------------------------------------------
// C tile 128x256, 512 threads, warps 4x4 (each 32x64), K-chunk 32, 2-stage.
// A smem: [128 m][32 k] pitch 80B  (normal ldmatrix)
// B smem: [32 k][256 n] pitch 528B (row-major, ldmatrix.trans)
static constexpr int PITCHA = 80;
static constexpr int MATA   = 128 * PITCHA;      // 10240
static constexpr int PITCHB = 528;               // 512B data + 16B pad
static constexpr int MATB   = 32 * PITCHB;       // 16896
static constexpr int STAGE  = MATA + MATB;       // 27136
static constexpr int DSM    = 2 * STAGE + 1024 + 16;  // ~55.3 KB, 1 CTA/SM

template <int KD, int ND, bool SWISH>
__global__ void __launch_bounds__(512, 1)
k_mma(const __half* __restrict__ Aw, const __half* __restrict__ Bw,
      const float* __restrict__ bias, float* __restrict__ out) {
    int row0 = blockIdx.x * 128;
    int e = row0 >> 13;                      // SEG = 8192
    if ((row0 & (SEG - 1)) >= g_count[e]) return;
    int col0 = blockIdx.y * 256;

    extern __shared__ char smc[];
    uint32_t sb = smem_u32(smc);
    float* sbias = reinterpret_cast<float*>(smc + 2 * STAGE);

    int tid = threadIdx.x, lid = tid & 31, wid = tid >> 5;
    int wm = wid >> 2, wn = wid & 3;         // 4 x 4 warps, each 32 x 64

    if (tid < 256) sbias[tid] = bias[(size_t)e * ND + col0 + tid];

    const __half* Ah = Aw + (size_t)row0 * KD;
    const __half* Bh = Bw + (size_t)e * KD * ND + col0;   // [K][N], row stride ND

    // per chunk: A 128x64B = 512 ops ; B 32x512B = 1024 ops ; 1536/512thr = 3 each
    auto copy_chunk = [&](uint32_t stage_base, int k0) {
        #pragma unroll
        for (int t = 0; t < 3; t++) {
            int i = tid + t * 512;
            if (i < 512) {                     // A
                int r = i >> 2, c = i & 3;
                const __half* src = Ah + (size_t)r * KD + k0 + c * 8;
                CP_ASYNC16(stage_base + r * PITCHA + c * 16, src);
            } else {                           // B
                int j = i - 512;
                int r = j >> 5, c = j & 31;
                const __half* src = Bh + (size_t)(k0 + r) * ND + c * 8;
                CP_ASYNC16(stage_base + MATA + r * PITCHB + c * 16, src);
            }
        }
    };

    float acc[2][8][4];
    #pragma unroll
    for (int a = 0; a < 2; a++)
        #pragma unroll
        for (int b = 0; b < 8; b++)
            #pragma unroll
            for (int q = 0; q < 4; q++) acc[a][b][q] = 0.f;

    const int NCH = KD / 32;
    copy_chunk(sb, 0); CP_COMMIT();
    copy_chunk(sb + STAGE, 32); CP_COMMIT();

    uint32_t lane_off_a = (uint32_t)((lid & 15) * PITCHA + (lid >> 4) * 16);
    uint32_t lane_off_b = (uint32_t)((lid & 15) * PITCHB + (lid >> 4) * 16);

    for (int cch = 0; cch < NCH; cch++) {
        if (cch + 1 < NCH) { CP_WAIT1(); } else { CP_WAIT0(); }
        __syncthreads();
        uint32_t st = sb + (cch & 1) * STAGE;
        #pragma unroll
        for (int kt = 0; kt < 2; kt++) {
            uint32_t af[2][4], bfr[4][4];
            #pragma unroll
            for (int mi = 0; mi < 2; mi++)
                ldm_x4(af[mi], st + (wm * 32 + mi * 16) * PITCHA + kt * 32 + lane_off_a);
            #pragma unroll
            for (int pr = 0; pr < 4; pr++)
                ldm_x4_t(bfr[pr], st + MATA + kt * 16 * PITCHB
                                  + (wn * 64 + pr * 16) * 2 + lane_off_b);
            #pragma unroll
            for (int pr = 0; pr < 4; pr++)
                #pragma unroll
                for (int mi = 0; mi < 2; mi++) {
                    mma16816(acc[mi][pr * 2],     af[mi], bfr[pr][0], bfr[pr][1]);
                    mma16816(acc[mi][pr * 2 + 1], af[mi], bfr[pr][2], bfr[pr][3]);
                }
        }
        __syncthreads();
        if (cch + 2 < NCH) { copy_chunk(sb + (cch & 1) * STAGE, (cch + 2) * 32); CP_COMMIT(); }
    }

    // ---- epilogue ----
    #pragma unroll
    for (int mi = 0; mi < 2; mi++) {
        #pragma unroll
        for (int ni = 0; ni < 8; ni++) {
            int ccol = wn * 64 + ni * 8 + (lid & 3) * 2;
            #pragma unroll
            for (int h = 0; h < 2; h++) {
                int lrow = wm * 32 + mi * 16 + (lid >> 2) + h * 8;
                int grow = row0 + lrow;
                float v0 = acc[mi][ni][h * 2]     + sbias[ccol];
                float v1 = acc[mi][ni][h * 2 + 1] + sbias[ccol + 1];
                if (SWISH) {
                    v0 = v0 / (1.0f + expf(-v0));
                    v1 = v1 / (1.0f + expf(-v1));
                    size_t idx = (size_t)grow * ND + col0 + ccol;
                    *reinterpret_cast<uint32_t*>(g_h + idx) =
                        pack2h(__float2half(v0), __float2half(v1));
                } else {
                    int slot = g_rowslot[grow];
                    if (slot >= 0) {
                        // out[token] += y ; exactly two fp32 contributions per token,
                        // addition commutative -> deterministic.
                        float* op = out + (size_t)(slot >> 1) * DDIM + col0 + ccol;
                        atomicAdd(op,     v0);
                        atomicAdd(op + 1, v1);
                    }
                }
            }
        }
    }
}

// -----------------------------------------------------------------------------
extern "C" void kernel_launch(void* const* d_in, const int* in_sizes, int n_in,
                              void* d_out, int out_size) {
    const float* x  = (const float*)d_in[0];
    const float* Wg = (const float*)d_in[1];
    const float* bg = (const float*)d_in[2];
    const float* W1 = (const float*)d_in[3];
    const float* b1 = (const float*)d_in[4];
    const float* W2 = (const float*)d_in[5];
    const float* b2 = (const float*)d_in[6];
    float* out = (float*)d_out;

    __half *ap, *hp, *w1p, *w2p;
    cudaGetSymbolAddress((void**)&ap, g_a);
    cudaGetSymbolAddress((void**)&hp, g_h);
    cudaGetSymbolAddress((void**)&w1p, g_w1);
    cudaGetSymbolAddress((void**)&w2p, g_w2);

    cudaFuncSetAttribute(k_mma<DDIM, FDIM, true>,  cudaFuncAttributeMaxDynamicSharedMemorySize, DSM);
    cudaFuncSetAttribute(k_mma<FDIM, DDIM, false>, cudaFuncAttributeMaxDynamicSharedMemorySize, DSM);

    k_prep<<<(NPREP + 255) / 256, 256>>>(W1, W2, out);
    k_gate<<<NTOK, 128>>>(x, Wg, bg);
    k_pack<<<RTOT, 128>>>(x);

    dim3 g1(RTOT / 128, FDIM / 256);   // (256, 16), empty row-tiles exit early
    k_mma<DDIM, FDIM, true><<<g1, 512, DSM>>>(ap, w1p, b1, nullptr);
    dim3 g2(RTOT / 128, DDIM / 256);   // (256, 4)
    k_mma<FDIM, DDIM, false><<<g2, 512, DSM>>>(hp, w2p, b2, out);
}

// round 16
// speedup vs baseline: 1.2445x; 1.2445x over previous
#include <cuda_runtime.h>
#include <cuda_fp16.h>
#include <cstdint>
#include <cmath>

#define NTOK 8192       // B*S
#define DDIM 1024
#define FDIM 4096
#define NEXP 4
#define SEG  8192       // fixed rows per expert segment
#define RTOT (NEXP * SEG)   // 32768 packed rows

// ---------------- device scratch (module-load; no runtime alloc) ------------
__device__ int g_count[NEXP];
__device__ int g_rowslot[RTOT];
__device__ __half g_a[(size_t)RTOT * DDIM];           // packed x as fp16
__device__ __half g_h[(size_t)RTOT * FDIM];           // h as fp16
__device__ __half g_w1[(size_t)NEXP * DDIM * FDIM];   // [E][D][F] fp16(W1)
__device__ __half g_w2[(size_t)NEXP * FDIM * DDIM];   // [E][F][D] fp16(W2)

// ---------------- helpers ----------------------------------------------------
__device__ __forceinline__ uint32_t smem_u32(const void* p) {
    uint32_t a;
    asm("{ .reg .u64 t; cvta.to.shared.u64 t, %1; cvt.u32.u64 %0, t; }" : "=r"(a) : "l"(p));
    return a;
}
#define CP_ASYNC16(dst, src) \
    asm volatile("cp.async.cg.shared.global [%0], [%1], 16;" :: "r"(dst), "l"(src))
#define CP_COMMIT() asm volatile("cp.async.commit_group;" ::: "memory")
#define CP_WAIT1()  asm volatile("cp.async.wait_group 1;" ::: "memory")
#define CP_WAIT0()  asm volatile("cp.async.wait_group 0;" ::: "memory")

__device__ __forceinline__ void ldm_x4(uint32_t* r, uint32_t addr) {
    asm volatile("ldmatrix.sync.aligned.m8n8.x4.shared.b16 {%0,%1,%2,%3}, [%4];"
                 : "=r"(r[0]), "=r"(r[1]), "=r"(r[2]), "=r"(r[3]) : "r"(addr));
}
__device__ __forceinline__ void ldm_x4_t(uint32_t* r, uint32_t addr) {
    asm volatile("ldmatrix.sync.aligned.m8n8.x4.trans.shared.b16 {%0,%1,%2,%3}, [%4];"
                 : "=r"(r[0]), "=r"(r[1]), "=r"(r[2]), "=r"(r[3]) : "r"(addr));
}
__device__ __forceinline__ void mma16816(float* c, const uint32_t* a, uint32_t b0, uint32_t b1) {
    asm("mma.sync.aligned.m16n8k16.row.col.f32.f16.f16.f32 "
        "{%0,%1,%2,%3}, {%4,%5,%6,%7}, {%8,%9}, {%0,%1,%2,%3};"
        : "+f"(c[0]), "+f"(c[1]), "+f"(c[2]), "+f"(c[3])
        : "r"(a[0]), "r"(a[1]), "r"(a[2]), "r"(a[3]), "r"(b0), "r"(b1));
}
__device__ __forceinline__ uint32_t pack2h(__half a, __half b) {
    return (uint32_t)__half_as_ushort(a) | ((uint32_t)__half_as_ushort(b) << 16);
}

// ---------------- prep: reset counters + zero out + cvt W1,W2 (one launch) ---
static constexpr int NW4   = NEXP * DDIM * FDIM / 4;
static constexpr int NOUT4 = NTOK * DDIM / 4;
static constexpr int NPREP = 2 * NW4 + NOUT4;

__global__ void k_prep(const float* __restrict__ W1, const float* __restrict__ W2,
                       float* __restrict__ out) {
    int i = blockIdx.x * blockDim.x + threadIdx.x;
    if (i < 4) g_count[i] = 0;
    if (i >= NPREP) return;
    if (i < NW4) {
        float4 v = reinterpret_cast<const float4*>(W1)[i];
        reinterpret_cast<uint2*>(g_w1)[i] =
            make_uint2(pack2h(__float2half(v.x), __float2half(v.y)),
                       pack2h(__float2half(v.z), __float2half(v.w)));
    } else if (i < 2 * NW4) {
        int j = i - NW4;
        float4 v = reinterpret_cast<const float4*>(W2)[j];
        reinterpret_cast<uint2*>(g_w2)[j] =
            make_uint2(pack2h(__float2half(v.x), __float2half(v.y)),
                       pack2h(__float2half(v.z), __float2half(v.w)));
    } else {
        reinterpret_cast<float4*>(out)[i - 2 * NW4] = make_float4(0.f, 0.f, 0.f, 0.f);
    }
}

// ---------------- gate + pack fused -------------------------------------------
// One block per token: top-2 gate, then convert+scatter the fp16 row into
// both experts' fixed segments directly.
__global__ void k_gate(const float* __restrict__ x, const float* __restrict__ Wg,
                       const float* __restrict__ bg) {
    int t = blockIdx.x, tid = threadIdx.x;
    const float* xr = x + (size_t)t * DDIM;
    float s0 = 0.f, s1 = 0.f, s2 = 0.f, s3 = 0.f;
    for (int i = tid; i < DDIM; i += 128) {
        float xv = xr[i];
        float4 w = *reinterpret_cast<const float4*>(Wg + (size_t)i * 4);
        s0 += xv * w.x; s1 += xv * w.y; s2 += xv * w.z; s3 += xv * w.w;
    }
    #pragma unroll
    for (int o = 16; o; o >>= 1) {
        s0 += __shfl_down_sync(~0u, s0, o); s1 += __shfl_down_sync(~0u, s1, o);
        s2 += __shfl_down_sync(~0u, s2, o); s3 += __shfl_down_sync(~0u, s3, o);
    }
    __shared__ float red[4][4];
    __shared__ int rowdst[2];
    if ((tid & 31) == 0) { int w = tid >> 5; red[w][0]=s0; red[w][1]=s1; red[w][2]=s2; red[w][3]=s3; }
    __syncthreads();
    if (tid == 0) {
        float l[4];
        #pragma unroll
        for (int e = 0; e < 4; e++) l[e] = red[0][e]+red[1][e]+red[2][e]+red[3][e]+bg[e];
        int e0 = 0;
        #pragma unroll
        for (int e = 1; e < 4; e++) if (l[e] > l[e0]) e0 = e;
        int e1 = -1;
        #pragma unroll
        for (int e = 0; e < 4; e++) { if (e == e0) continue; if (e1 < 0 || l[e] > l[e1]) e1 = e; }
        int p0 = atomicAdd(&g_count[e0], 1);
        int p1 = atomicAdd(&g_count[e1], 1);
        int r0 = e0 * SEG + p0;
        int r1 = e1 * SEG + p1;
        g_rowslot[r0] = t * 2;
        g_rowslot[r1] = t * 2 + 1;
        rowdst[0] = r0; rowdst[1] = r1;
    }
    __syncthreads();
    // convert the x row once, write to both packed rows
    const float4* src = reinterpret_cast<const float4*>(xr);
    float4 v0 = src[tid * 2], v1 = src[tid * 2 + 1];
    uint4 uh = make_uint4(
        pack2h(__float2half(v0.x), __float2half(v0.y)),
        pack2h(__float2half(v0.z), __float2half(v0.w)),
        pack2h(__float2half(v1.x), __float2half(v1.y)),
        pack2h(__float2half(v1.z), __float2half(v1.w)));
    *reinterpret_cast<uint4*>(g_a + (size_t)rowdst[0] * DDIM + tid * 8) = uh;
    *reinterpret_cast<uint4*>(g_a + (size_t)rowdst[1] * DDIM + tid * 8) = uh;
}

// ---------------- pad: zero rows [cnt, align128(cnt)) per expert --------------
__global__ void k_pad() {
    int e = blockIdx.x;
    int cnt = g_count[e];
    int top = (cnt + 127) & ~127;
    int tid = threadIdx.x;
    for (int j = cnt; j < top; j++) {
        int b = e * SEG + j;
        if (tid == 0) g_rowslot[b] = -1;
        *reinterpret_cast<uint4*>(g_a + (size_t)b * DDIM + tid * 8) = make_uint4(0, 0, 0, 0);
    }
}

// ---------------- HMMA grouped GEMM (R14 config: 128x128, 2 CTAs/SM) ----------
static constexpr int PITCHA = 80;
static constexpr int MATA   = 128 * PITCHA;      // 10240
static constexpr int PITCHB = 272;               // 256B data + 16B pad
static constexpr int MATB   = 32 * PITCHB;       // 8704
static constexpr int STAGE  = MATA + MATB;       // 18944
static constexpr int DSM    = 2 * STAGE + 512 + 16;  // ~38.5 KB -> 2 CTAs/SM

template <int KD, int ND, bool SWISH>
__global__ void __launch_bounds__(256, 2)
k_mma(const __half* __restrict__ Aw, const __half* __restrict__ Bw,
      const float* __restrict__ bias, float* __restrict__ out) {
    int row0 = blockIdx.x * 128;
    int e = row0 >> 13;                      // SEG = 8192
    if ((row0 & (SEG - 1)) >= g_count[e]) return;
    int col0 = blockIdx.y * 128;

    extern __shared__ char smc[];
    uint32_t sb = smem_u32(smc);
    float* sbias = reinterpret_cast<float*>(smc + 2 * STAGE);

    int tid = threadIdx.x, lid = tid & 31, wid = tid >> 5;
    int wm = wid >> 1, wn = wid & 1;

    if (tid < 128) sbias[tid] = bias[(size_t)e * ND + col0 + tid];

    const __half* Ah = Aw + (size_t)row0 * KD;
    const __half* Bh = Bw + (size_t)e * KD * ND + col0;   // [K][N], row stride ND

    auto copy_chunk = [&](uint32_t stage_base, int k0) {
        #pragma unroll
        for (int t = 0; t < 4; t++) {
            int i = tid + t * 256;
            if (i < 512) {                     // A: 128 rows x 64B
                int r = i >> 2, c = i & 3;
                const __half* src = Ah + (size_t)r * KD + k0 + c * 8;
                CP_ASYNC16(stage_base + r * PITCHA + c * 16, src);
            } else {                           // B: 32 rows x 256B
                int j = i - 512;
                int r = j >> 4, c = j & 15;
                const __half* src = Bh + (size_t)(k0 + r) * ND + c * 8;
                CP_ASYNC16(stage_base + MATA + r * PITCHB + c * 16, src);
            }
        }
    };

    float acc[2][8][4];
    #pragma unroll
    for (int a = 0; a < 2; a++)
        #pragma unroll
        for (int b = 0; b < 8; b++)
            #pragma unroll
            for (int q = 0; q < 4; q++) acc[a][b][q] = 0.f;

    const int NCH = KD / 32;
    copy_chunk(sb, 0); CP_COMMIT();
    copy_chunk(sb + STAGE, 32); CP_COMMIT();

    uint32_t lane_off_a = (uint32_t)((lid & 15) * PITCHA + (lid >> 4) * 16);
    uint32_t lane_off_b = (uint32_t)((lid & 15) * PITCHB + (lid >> 4) * 16);

    for (int cch = 0; cch < NCH; cch++) {
        if (cch + 1 < NCH) { CP_WAIT1(); } else { CP_WAIT0(); }
        __syncthreads();
        uint32_t st = sb + (cch & 1) * STAGE;
        #pragma unroll
        for (int kt = 0; kt < 2; kt++) {
            uint32_t af[2][4], bfr[4][4];
            #pragma unroll
            for (int mi = 0; mi < 2; mi++)
                ldm_x4(af[mi], st + (wm * 32 + mi * 16) * PITCHA + kt * 32 + lane_off_a);
            #pragma unroll
            for (int pr = 0; pr < 4; pr++)
                ldm_x4_t(bfr[pr], st + MATA + kt * 16 * PITCHB
                                  + (wn * 64 + pr * 16) * 2 + lane_off_b);
            #pragma unroll
            for (int pr = 0; pr < 4; pr++)
                #pragma unroll
                for (int mi = 0; mi < 2; mi++) {
                    mma16816(acc[mi][pr * 2],     af[mi], bfr[pr][0], bfr[pr][1]);
                    mma16816(acc[mi][pr * 2 + 1], af[mi], bfr[pr][2], bfr[pr][3]);
                }
        }
        __syncthreads();
        if (cch + 2 < NCH) { copy_chunk(sb + (cch & 1) * STAGE, (cch + 2) * 32); CP_COMMIT(); }
    }

    // ---- epilogue ----
    #pragma unroll
    for (int mi = 0; mi < 2; mi++) {
        #pragma unroll
        for (int ni = 0; ni < 8; ni++) {
            int ccol = wn * 64 + ni * 8 + (lid & 3) * 2;
            #pragma unroll
            for (int h = 0; h < 2; h++) {
                int lrow = wm * 32 + mi * 16 + (lid >> 2) + h * 8;
                int grow = row0 + lrow;
                float v0 = acc[mi][ni][h * 2]     + sbias[ccol];
                float v1 = acc[mi][ni][h * 2 + 1] + sbias[ccol + 1];
                if (SWISH) {
                    v0 = v0 / (1.0f + expf(-v0));
                    v1 = v1 / (1.0f + expf(-v1));
                    size_t idx = (size_t)grow * ND + col0 + ccol;
                    *reinterpret_cast<uint32_t*>(g_h + idx) =
                        pack2h(__float2half(v0), __float2half(v1));
                } else {
                    int slot = g_rowslot[grow];
                    if (slot >= 0) {
                        // out[token] += y ; exactly two fp32 contributions per token,
                        // addition commutative -> deterministic.
                        float* op = out + (size_t)(slot >> 1) * DDIM + col0 + ccol;
                        atomicAdd(op,     v0);
                        atomicAdd(op + 1, v1);
                    }
                }
            }
        }
    }
}

// -----------------------------------------------------------------------------
extern "C" void kernel_launch(void* const* d_in, const int* in_sizes, int n_in,
                              void* d_out, int out_size) {
    const float* x  = (const float*)d_in[0];
    const float* Wg = (const float*)d_in[1];
    const float* bg = (const float*)d_in[2];
    const float* W1 = (const float*)d_in[3];
    const float* b1 = (const float*)d_in[4];
    const float* W2 = (const float*)d_in[5];
    const float* b2 = (const float*)d_in[6];
    float* out = (float*)d_out;

    __half *ap, *hp, *w1p, *w2p;
    cudaGetSymbolAddress((void**)&ap, g_a);
    cudaGetSymbolAddress((void**)&hp, g_h);
    cudaGetSymbolAddress((void**)&w1p, g_w1);
    cudaGetSymbolAddress((void**)&w2p, g_w2);

    cudaFuncSetAttribute(k_mma<DDIM, FDIM, true>,  cudaFuncAttributeMaxDynamicSharedMemorySize, DSM);
    cudaFuncSetAttribute(k_mma<FDIM, DDIM, false>, cudaFuncAttributeMaxDynamicSharedMemorySize, DSM);

    k_prep<<<(NPREP + 255) / 256, 256>>>(W1, W2, out);
    k_gate<<<NTOK, 128>>>(x, Wg, bg);
    k_pad<<<NEXP, 128>>>();

    dim3 g1(RTOT / 128, FDIM / 128);   // (256, 32), empty row-tiles exit early
    k_mma<DDIM, FDIM, true><<<g1, 256, DSM>>>(ap, w1p, b1, nullptr);
    dim3 g2(RTOT / 128, DDIM / 128);   // (256, 8)
    k_mma<FDIM, DDIM, false><<<g2, 256, DSM>>>(hp, w2p, b2, out);
}

// round 17
// speedup vs baseline: 1.2710x; 1.0212x over previous
#include <cuda_runtime.h>
#include <cuda_fp16.h>
#include <cstdint>
#include <cmath>

#define NTOK 8192       // B*S
#define DDIM 1024
#define FDIM 4096
#define NEXP 4
#define SEG  8192       // fixed rows per expert segment
#define RTOT (NEXP * SEG)   // 32768 packed rows

// ---------------- device scratch (module-load; no runtime alloc) ------------
__device__ int g_count[NEXP];
__device__ int g_rowslot[RTOT];
__device__ __half g_a[(size_t)RTOT * DDIM];           // packed x as fp16
__device__ __half g_h[(size_t)RTOT * FDIM];           // h as fp16
__device__ __half g_w1[(size_t)NEXP * DDIM * FDIM];   // [E][D][F] fp16(W1)
__device__ __half g_w2[(size_t)NEXP * FDIM * DDIM];   // [E][F][D] fp16(W2)

// ---------------- helpers ----------------------------------------------------
__device__ __forceinline__ uint32_t smem_u32(const void* p) {
    uint32_t a;
    asm("{ .reg .u64 t; cvta.to.shared.u64 t, %1; cvt.u32.u64 %0, t; }" : "=r"(a) : "l"(p));
    return a;
}
#define CP_ASYNC16(dst, src) \
    asm volatile("cp.async.cg.shared.global [%0], [%1], 16;" :: "r"(dst), "l"(src))
#define CP_COMMIT() asm volatile("cp.async.commit_group;" ::: "memory")
#define CP_WAIT1()  asm volatile("cp.async.wait_group 1;" ::: "memory")
#define CP_WAIT0()  asm volatile("cp.async.wait_group 0;" ::: "memory")

__device__ __forceinline__ void ldm_x4(uint32_t* r, uint32_t addr) {
    asm volatile("ldmatrix.sync.aligned.m8n8.x4.shared.b16 {%0,%1,%2,%3}, [%4];"
                 : "=r"(r[0]), "=r"(r[1]), "=r"(r[2]), "=r"(r[3]) : "r"(addr));
}
__device__ __forceinline__ void ldm_x4_t(uint32_t* r, uint32_t addr) {
    asm volatile("ldmatrix.sync.aligned.m8n8.x4.trans.shared.b16 {%0,%1,%2,%3}, [%4];"
                 : "=r"(r[0]), "=r"(r[1]), "=r"(r[2]), "=r"(r[3]) : "r"(addr));
}
__device__ __forceinline__ void mma16816(float* c, const uint32_t* a, uint32_t b0, uint32_t b1) {
    asm("mma.sync.aligned.m16n8k16.row.col.f32.f16.f16.f32 "
        "{%0,%1,%2,%3}, {%4,%5,%6,%7}, {%8,%9}, {%0,%1,%2,%3};"
        : "+f"(c[0]), "+f"(c[1]), "+f"(c[2]), "+f"(c[3])
        : "r"(a[0]), "r"(a[1]), "r"(a[2]), "r"(a[3]), "r"(b0), "r"(b1));
}
__device__ __forceinline__ uint32_t pack2h(__half a, __half b) {
    return (uint32_t)__half_as_ushort(a) | ((uint32_t)__half_as_ushort(b) << 16);
}

// ---------------- prep: counters + rowslot reset + zero out + cvt W1,W2 ------
static constexpr int NW4   = NEXP * DDIM * FDIM / 4;
static constexpr int NOUT4 = NTOK * DDIM / 4;
static constexpr int NPREP = 2 * NW4 + NOUT4;

__global__ void k_prep(const float* __restrict__ W1, const float* __restrict__ W2,
                       float* __restrict__ out) {
    int i = blockIdx.x * blockDim.x + threadIdx.x;
    if (i < 4) g_count[i] = 0;
    if (i < RTOT) g_rowslot[i] = -1;     // pad/garbage rows stay discarded
    if (i >= NPREP) return;
    if (i < NW4) {
        float4 v = reinterpret_cast<const float4*>(W1)[i];
        reinterpret_cast<uint2*>(g_w1)[i] =
            make_uint2(pack2h(__float2half(v.x), __float2half(v.y)),
                       pack2h(__float2half(v.z), __float2half(v.w)));
    } else if (i < 2 * NW4) {
        int j = i - NW4;
        float4 v = reinterpret_cast<const float4*>(W2)[j];
        reinterpret_cast<uint2*>(g_w2)[j] =
            make_uint2(pack2h(__float2half(v.x), __float2half(v.y)),
                       pack2h(__float2half(v.z), __float2half(v.w)));
    } else {
        reinterpret_cast<float4*>(out)[i - 2 * NW4] = make_float4(0.f, 0.f, 0.f, 0.f);
    }
}

// ---------------- gate + pack fused -------------------------------------------
__global__ void k_gate(const float* __restrict__ x, const float* __restrict__ Wg,
                       const float* __restrict__ bg) {
    int t = blockIdx.x, tid = threadIdx.x;
    const float* xr = x + (size_t)t * DDIM;
    float s0 = 0.f, s1 = 0.f, s2 = 0.f, s3 = 0.f;
    for (int i = tid; i < DDIM; i += 128) {
        float xv = xr[i];
        float4 w = *reinterpret_cast<const float4*>(Wg + (size_t)i * 4);
        s0 += xv * w.x; s1 += xv * w.y; s2 += xv * w.z; s3 += xv * w.w;
    }
    #pragma unroll
    for (int o = 16; o; o >>= 1) {
        s0 += __shfl_down_sync(~0u, s0, o); s1 += __shfl_down_sync(~0u, s1, o);
        s2 += __shfl_down_sync(~0u, s2, o); s3 += __shfl_down_sync(~0u, s3, o);
    }
    __shared__ float red[4][4];
    __shared__ int rowdst[2];
    if ((tid & 31) == 0) { int w = tid >> 5; red[w][0]=s0; red[w][1]=s1; red[w][2]=s2; red[w][3]=s3; }
    __syncthreads();
    if (tid == 0) {
        float l[4];
        #pragma unroll
        for (int e = 0; e < 4; e++) l[e] = red[0][e]+red[1][e]+red[2][e]+red[3][e]+bg[e];
        int e0 = 0;
        #pragma unroll
        for (int e = 1; e < 4; e++) if (l[e] > l[e0]) e0 = e;
        int e1 = -1;
        #pragma unroll
        for (int e = 0; e < 4; e++) { if (e == e0) continue; if (e1 < 0 || l[e] > l[e1]) e1 = e; }
        int p0 = atomicAdd(&g_count[e0], 1);
        int p1 = atomicAdd(&g_count[e1], 1);
        int r0 = e0 * SEG + p0;
        int r1 = e1 * SEG + p1;
        g_rowslot[r0] = t * 2;
        g_rowslot[r1] = t * 2 + 1;
        rowdst[0] = r0; rowdst[1] = r1;
    }
    __syncthreads();
    const float4* src = reinterpret_cast<const float4*>(xr);
    float4 v0 = src[tid * 2], v1 = src[tid * 2 + 1];
    uint4 uh = make_uint4(
        pack2h(__float2half(v0.x), __float2half(v0.y)),
        pack2h(__float2half(v0.z), __float2half(v0.w)),
        pack2h(__float2half(v1.x), __float2half(v1.y)),
        pack2h(__float2half(v1.z), __float2half(v1.w)));
    *reinterpret_cast<uint4*>(g_a + (size_t)rowdst[0] * DDIM + tid * 8) = uh;
    *reinterpret_cast<uint4*>(g_a + (size_t)rowdst[1] * DDIM + tid * 8) = uh;
}

// ---------------- HMMA grouped GEMM (128x128, 2 CTAs/SM) ----------------------
static constexpr int PITCHA = 80;
static constexpr int MATA   = 128 * PITCHA;      // 10240
static constexpr int PITCHB = 272;               // 256B data + 16B pad
static constexpr int MATB   = 32 * PITCHB;       // 8704
static constexpr int STAGE  = MATA + MATB;       // 18944
static constexpr int DSM    = 2 * STAGE + 512 + 16;  // ~38.5 KB -> 2 CTAs/SM

template <int KD, int ND, bool SWISH>
__global__ void __launch_bounds__(256, 2)
k_mma(const __half* __restrict__ Aw, const __half* __restrict__ Bw,
      const float* __restrict__ bias, float* __restrict__ out) {
    int row0 = blockIdx.x * 128;
    int e = row0 >> 13;                      // SEG = 8192
    if ((row0 & (SEG - 1)) >= g_count[e]) return;
    int col0 = blockIdx.y * 128;

    extern __shared__ char smc[];
    uint32_t sb = smem_u32(smc);
    float* sbias = reinterpret_cast<float*>(smc + 2 * STAGE);

    int tid = threadIdx.x, lid = tid & 31, wid = tid >> 5;
    int wm = wid >> 1, wn = wid & 1;

    if (tid < 128) sbias[tid] = bias[(size_t)e * ND + col0 + tid];

    const __half* Ah = Aw + (size_t)row0 * KD;
    const __half* Bh = Bw + (size_t)e * KD * ND + col0;   // [K][N], row stride ND

    auto copy_chunk = [&](uint32_t stage_base, int k0) {
        #pragma unroll
        for (int t = 0; t < 4; t++) {
            int i = tid + t * 256;
            if (i < 512) {                     // A: 128 rows x 64B
                int r = i >> 2, c = i & 3;
                const __half* src = Ah + (size_t)r * KD + k0 + c * 8;
                CP_ASYNC16(stage_base + r * PITCHA + c * 16, src);
            } else {                           // B: 32 rows x 256B
                int j = i - 512;
                int r = j >> 4, c = j & 15;
                const __half* src = Bh + (size_t)(k0 + r) * ND + c * 8;
                CP_ASYNC16(stage_base + MATA + r * PITCHB + c * 16, src);
            }
        }
    };

    float acc[2][8][4];
    #pragma unroll
    for (int a = 0; a < 2; a++)
        #pragma unroll
        for (int b = 0; b < 8; b++)
            #pragma unroll
            for (int q = 0; q < 4; q++) acc[a][b][q] = 0.f;

    const int NCH = KD / 32;
    copy_chunk(sb, 0); CP_COMMIT();
    copy_chunk(sb + STAGE, 32); CP_COMMIT();

    uint32_t lane_off_a = (uint32_t)((lid & 15) * PITCHA + (lid >> 4) * 16);
    uint32_t lane_off_b = (uint32_t)((lid & 15) * PITCHB + (lid >> 4) * 16);

    for (int cch = 0; cch < NCH; cch++) {
        if (cch + 1 < NCH) { CP_WAIT1(); } else { CP_WAIT0(); }
        __syncthreads();
        uint32_t st = sb + (cch & 1) * STAGE;
        #pragma unroll
        for (int kt = 0; kt < 2; kt++) {
            uint32_t af[2][4], bfr[4][4];
            #pragma unroll
            for (int mi = 0; mi < 2; mi++)
                ldm_x4(af[mi], st + (wm * 32 + mi * 16) * PITCHA + kt * 32 + lane_off_a);
            #pragma unroll
            for (int pr = 0; pr < 4; pr++)
                ldm_x4_t(bfr[pr], st + MATA + kt * 16 * PITCHB
                                  + (wn * 64 + pr * 16) * 2 + lane_off_b);
            #pragma unroll
            for (int pr = 0; pr < 4; pr++)
                #pragma unroll
                for (int mi = 0; mi < 2; mi++) {
                    mma16816(acc[mi][pr * 2],     af[mi], bfr[pr][0], bfr[pr][1]);
                    mma16816(acc[mi][pr * 2 + 1], af[mi], bfr[pr][2], bfr[pr][3]);
                }
        }
        __syncthreads();
        if (cch + 2 < NCH) { copy_chunk(sb + (cch & 1) * STAGE, (cch + 2) * 32); CP_COMMIT(); }
    }

    // ---- epilogue ----
    #pragma unroll
    for (int mi = 0; mi < 2; mi++) {
        #pragma unroll
        for (int ni = 0; ni < 8; ni++) {
            int ccol = wn * 64 + ni * 8 + (lid & 3) * 2;
            #pragma unroll
            for (int h = 0; h < 2; h++) {
                int lrow = wm * 32 + mi * 16 + (lid >> 2) + h * 8;
                int grow = row0 + lrow;
                float v0 = acc[mi][ni][h * 2]     + sbias[ccol];
                float v1 = acc[mi][ni][h * 2 + 1] + sbias[ccol + 1];
                if (SWISH) {
                    v0 = v0 / (1.0f + expf(-v0));
                    v1 = v1 / (1.0f + expf(-v1));
                    size_t idx = (size_t)grow * ND + col0 + ccol;
                    *reinterpret_cast<uint32_t*>(g_h + idx) =
                        pack2h(__float2half(v0), __float2half(v1));
                } else {
                    int slot = g_rowslot[grow];
                    if (slot >= 0) {
                        // out[token] += y ; exactly two fp32 contributions per token,
                        // addition commutative -> deterministic. Vector RED.64.
                        float2* op = reinterpret_cast<float2*>(
                            out + (size_t)(slot >> 1) * DDIM + col0 + ccol);
                        atomicAdd(op, make_float2(v0, v1));
                    }
                }
            }
        }
    }
}

// -----------------------------------------------------------------------------
extern "C" void kernel_launch(void* const* d_in, const int* in_sizes, int n_in,
                              void* d_out, int out_size) {
    const float* x  = (const float*)d_in[0];
    const float* Wg = (const float*)d_in[1];
    const float* bg = (const float*)d_in[2];
    const float* W1 = (const float*)d_in[3];
    const float* b1 = (const float*)d_in[4];
    const float* W2 = (const float*)d_in[5];
    const float* b2 = (const float*)d_in[6];
    float* out = (float*)d_out;

    __half *ap, *hp, *w1p, *w2p;
    cudaGetSymbolAddress((void**)&ap, g_a);
    cudaGetSymbolAddress((void**)&hp, g_h);
    cudaGetSymbolAddress((void**)&w1p, g_w1);
    cudaGetSymbolAddress((void**)&w2p, g_w2);

    cudaFuncSetAttribute(k_mma<DDIM, FDIM, true>,  cudaFuncAttributeMaxDynamicSharedMemorySize, DSM);
    cudaFuncSetAttribute(k_mma<FDIM, DDIM, false>, cudaFuncAttributeMaxDynamicSharedMemorySize, DSM);

    k_prep<<<(NPREP + 255) / 256, 256>>>(W1, W2, out);
    k_gate<<<NTOK, 128>>>(x, Wg, bg);

    dim3 g1(RTOT / 128, FDIM / 128);   // (256, 32), empty row-tiles exit early
    k_mma<DDIM, FDIM, true><<<g1, 256, DSM>>>(ap, w1p, b1, nullptr);
    dim3 g2(RTOT / 128, DDIM / 128);   // (256, 8)
    k_mma<FDIM, DDIM, false><<<g2, 256, DSM>>>(hp, w2p, b2, out);
}